// round 6
// baseline (speedup 1.0000x reference)
#include <cuda_runtime.h>
#include <math.h>

#define NVARS    22
#define NSTATES  (1 << NVARS)          // 4,194,304
#define LOWBITS  12
#define HIGHBITS 10
#define LOWN     (1 << LOWBITS)        // 4096
#define HIGHN    (1 << HIGHBITS)       // 1024
#define TLOW     4                     // low-index columns per kernelB tile
#define LPB      5                     // padded row stride for kernelB (float2)
#define THREADS  512

// Scratch statevector (32 MB) and reduction accumulator as device globals
// (no device allocation allowed anywhere).
__device__ float2 g_circ[NSTATES];
__device__ double g_sum;

__global__ void finalize_kernel(float* out) { out[0] = (float)g_sum; }

// ---------------------------------------------------------------------------
// Kernel A: butterflies over the low 12 bits; block = 4096 contiguous elems
// in 32 KB static smem.
// INIT=true : build initial state (1/2048)*exp(i*gamma[0]*h[x]) in-register,
//             and zero the reduction accumulator (block 0, thread 0).
// INIT=false: read g_circ (layer-1 phase already fused by kernelB<false>).
// ---------------------------------------------------------------------------
template <bool INIT>
__global__ void __launch_bounds__(THREADS)
kernelA(const float* __restrict__ h,
        const float* __restrict__ gamma,
        const float* __restrict__ beta,
        int layer)
{
    __shared__ float2 sh[LOWN];   // 32 KB

    const int tid  = threadIdx.x;
    const int base = blockIdx.x * LOWN;

    const float cb = cosf(beta[layer]);
    const float sb = sinf(beta[layer]);

    if (INIT) {
        if (blockIdx.x == 0 && tid == 0) g_sum = 0.0;   // stream-ordered zero
        const float s  = 1.0f / 2048.0f;   // 1/sqrt(2^22), exact in fp32
        const float g0 = gamma[0];
        #pragma unroll
        for (int k = 0; k < LOWN / THREADS; k++) {
            int i = tid + k * THREADS;
            float sp, cp;
            __sincosf(g0 * h[base + i], &sp, &cp);
            sh[i] = make_float2(s * cp, s * sp);
        }
    } else {
        #pragma unroll
        for (int k = 0; k < LOWN / THREADS; k++) {
            int i = tid + k * THREADS;
            sh[i] = g_circ[base + i];
        }
    }
    __syncthreads();

    for (int b = 0; b < LOWBITS; b++) {
        const int bit = 1 << b;
        #pragma unroll
        for (int k = 0; k < (LOWN / 2) / THREADS; k++) {   // 4 pairs/thread
            int p  = tid + k * THREADS;
            int i0 = ((p >> b) << (b + 1)) | (p & (bit - 1));
            int i1 = i0 | bit;
            float2 a = sh[i0];
            float2 c = sh[i1];
            // a' = cb*a + i*sb*c ; c' = cb*c + i*sb*a
            float2 na = make_float2(fmaf(cb, a.x, -sb * c.y),
                                    fmaf(cb, a.y,  sb * c.x));
            float2 nc = make_float2(fmaf(cb, c.x, -sb * a.y),
                                    fmaf(cb, c.y,  sb * a.x));
            sh[i0] = na;
            sh[i1] = nc;
        }
        __syncthreads();
    }

    #pragma unroll
    for (int k = 0; k < LOWN / THREADS; k++) {
        int i = tid + k * THREADS;
        g_circ[base + i] = sh[i];
    }
}

// ---------------------------------------------------------------------------
// Kernel B: butterflies over the high 10 bits. Tile = TLOW(4) consecutive
// low indices x 1024 high-stride rows (stride LOWN). Each global row access
// is a 32B-aligned 32B request (full DRAM sector utilization).
// Static smem: 1024 rows x LPB(5) float2 = 40,960 B  (< 48 KB default cap).
// LAST=false: fuse next layer's cost phase exp(i*gamma[layer+1]*h) on store.
// LAST=true : fuse the final sum(|c|^2 * hS) reduction (no store-back).
// ---------------------------------------------------------------------------
template <bool LAST>
__global__ void __launch_bounds__(THREADS)
kernelB(const float* __restrict__ h,
        const float* __restrict__ hS,
        const float* __restrict__ gamma,
        const float* __restrict__ beta,
        int layer)
{
    __shared__ float2 sh[HIGHN * LPB];   // 40 KB

    const int tid     = threadIdx.x;
    const int lowbase = blockIdx.x * TLOW;

    const float cb = cosf(beta[layer]);
    const float sb = sinf(beta[layer]);

    const int low = tid & (TLOW - 1);
    const int j0  = tid >> 2;            // 0..127

    // Load tile
    #pragma unroll
    for (int it = 0; it < HIGHN / (THREADS / TLOW); it++) {   // 8 iters
        int j = j0 + it * (THREADS / TLOW);
        sh[j * LPB + low] = g_circ[j * LOWN + lowbase + low];
    }
    __syncthreads();

    for (int b = 0; b < HIGHBITS; b++) {
        const int bit = 1 << b;
        #pragma unroll
        for (int it = 0; it < ((HIGHN / 2) * TLOW) / THREADS; it++) { // 4 iters
            int q  = tid + it * THREADS;
            int l  = q & (TLOW - 1);
            int jp = q >> 2;                       // 0..511 pair index
            int i0 = ((jp >> b) << (b + 1)) | (jp & (bit - 1));
            int i1 = i0 | bit;
            float2 a = sh[i0 * LPB + l];
            float2 c = sh[i1 * LPB + l];
            float2 na = make_float2(fmaf(cb, a.x, -sb * c.y),
                                    fmaf(cb, a.y,  sb * c.x));
            float2 nc = make_float2(fmaf(cb, c.x, -sb * a.y),
                                    fmaf(cb, c.y,  sb * a.x));
            sh[i0 * LPB + l] = na;
            sh[i1 * LPB + l] = nc;
        }
        __syncthreads();
    }

    if (!LAST) {
        // Apply next layer's cost phase at write-back.
        const float g1 = gamma[layer + 1];
        #pragma unroll
        for (int it = 0; it < HIGHN / (THREADS / TLOW); it++) {
            int j    = j0 + it * (THREADS / TLOW);
            int gidx = j * LOWN + lowbase + low;
            float2 v = sh[j * LPB + low];
            float sp, cp;
            __sincosf(g1 * h[gidx], &sp, &cp);
            g_circ[gidx] = make_float2(v.x * cp - v.y * sp,
                                       v.x * sp + v.y * cp);
        }
    } else {
        // Final reduction: sum |c|^2 * hS in double precision.
        double acc = 0.0;
        #pragma unroll
        for (int it = 0; it < HIGHN / (THREADS / TLOW); it++) {
            int j    = j0 + it * (THREADS / TLOW);
            int gidx = j * LOWN + lowbase + low;
            float2 v = sh[j * LPB + low];
            float p  = fmaf(v.x, v.x, v.y * v.y);
            acc += (double)p * (double)hS[gidx];
        }
        // warp reduce
        #pragma unroll
        for (int o = 16; o > 0; o >>= 1)
            acc += __shfl_down_sync(0xffffffffu, acc, o);
        __shared__ double warpsum[THREADS / 32];
        if ((tid & 31) == 0) warpsum[tid >> 5] = acc;
        __syncthreads();
        if (tid < THREADS / 32) {
            acc = warpsum[tid];
            #pragma unroll
            for (int o = (THREADS / 64); o > 0; o >>= 1)
                acc += __shfl_down_sync(0xffffu, acc, o);
            if (tid == 0) atomicAdd(&g_sum, acc);
        }
    }
}

extern "C" void kernel_launch(void* const* d_in, const int* in_sizes, int n_in,
                              void* d_out, int out_size)
{
    const float* h     = (const float*)d_in[0];
    const float* hS    = (const float*)d_in[1];
    const float* gamma = (const float*)d_in[2];
    const float* beta  = (const float*)d_in[3];
    float* out = (float*)d_out;

    const int gridA = NSTATES / LOWN;   // 1024
    const int gridB = LOWN / TLOW;      // 1024

    // Layer 0: init + phase(gamma0) + 12 low stages (also zeroes g_sum)
    kernelA<true><<<gridA, THREADS>>>(h, gamma, beta, 0);
    // Layer 0: 10 high stages + fused phase(gamma1)
    kernelB<false><<<gridB, THREADS>>>(h, hS, gamma, beta, 0);
    // Layer 1: 12 low stages
    kernelA<false><<<gridA, THREADS>>>(h, gamma, beta, 1);
    // Layer 1: 10 high stages + fused |c|^2 * hS reduction
    kernelB<true><<<gridB, THREADS>>>(h, hS, gamma, beta, 1);

    finalize_kernel<<<1, 1>>>(out);
}

// round 9
// speedup vs baseline: 1.4351x; 1.4351x over previous
#include <cuda_runtime.h>
#include <math.h>

#define NSTATES (1 << 22)      // 4,194,304 amplitudes
#define THREADS 512

// Scratch statevector (32 MB) and reduction accumulator as device globals.
__device__ float2 g_circ[NSTATES];
__device__ double g_sum;

__global__ void finalize_kernel(float* out) { out[0] = (float)g_sum; }

// Bank-conflict-free smem address swizzle. With this mapping, both access
// patterns used below (read a=k*512+t, write a=8t+k) are verified
// conflict-free for 64-bit LDS/STS across every 16-lane phase.
__device__ __forceinline__ int phi(int a) {
    return a ^ (((a >> 3) ^ (a >> 6)) & 7);
}

// One Rx-mixing butterfly on registers A,C:
//   A' = cb*A + i*sb*C ;  C' = cb*C + i*sb*A
#define BF(A, C) { float ax=v[A].x, ay=v[A].y, cx=v[C].x, cy=v[C].y; \
    v[A].x = fmaf(cb, ax, -sb * cy); v[A].y = fmaf(cb, ay,  sb * cx); \
    v[C].x = fmaf(cb, cx, -sb * ay); v[C].y = fmaf(cb, cy,  sb * ax); }

// 3 butterfly stages on the 3 k-bits of v[0..7]
#define RADIX8 { BF(0,1) BF(2,3) BF(4,5) BF(6,7) \
                 BF(0,2) BF(1,3) BF(4,6) BF(5,7) \
                 BF(0,4) BF(1,5) BF(2,6) BF(3,7) }

// ---------------------------------------------------------------------------
// Kernel A: 12 butterfly stages over the low 12 bits, block = 4096 contiguous
// amplitudes. 4 register-radix-8 rounds (3 stages each); between rounds the
// storage key rotates left by 3 bits so every round reads k*512+t and writes
// 8t+k (both conflict-free under phi). First round fused with global load,
// last round fused with global store (64B contiguous per thread).
// INIT=true: synthesize (1/2048)*exp(i*gamma0*h) in-register; also zero g_sum.
// ---------------------------------------------------------------------------
template <bool INIT>
__global__ void __launch_bounds__(THREADS)
kernelA(const float* __restrict__ h,
        const float* __restrict__ gamma,
        const float* __restrict__ beta,
        int layer)
{
    __shared__ float2 sh[4096];   // 32 KB, no padding needed (phi is in-place)

    const int t    = threadIdx.x;
    const int base = blockIdx.x << 12;
    const float cb = cosf(beta[layer]);
    const float sb = sinf(beta[layer]);
    float2 v[8];

    if (INIT) {
        if (blockIdx.x == 0 && t == 0) g_sum = 0.0;   // stream-ordered zero
        const float s  = 1.0f / 2048.0f;               // 1/sqrt(2^22)
        const float g0 = gamma[0];
        #pragma unroll
        for (int k = 0; k < 8; k++) {                  // coalesced: 128B/warp
            float sp, cp;
            __sincosf(g0 * h[base + k * 512 + t], &sp, &cp);
            v[k] = make_float2(s * cp, s * sp);
        }
    } else {
        #pragma unroll
        for (int k = 0; k < 8; k++)                    // coalesced: 256B/warp
            v[k] = g_circ[base + k * 512 + t];
    }
    RADIX8;                                            // logical bits 9..11
    #pragma unroll
    for (int k = 0; k < 8; k++) sh[phi(t * 8 + k)] = v[k];
    __syncthreads();

    #pragma unroll
    for (int r = 0; r < 2; r++) {                      // bits 6..8, then 3..5
        #pragma unroll
        for (int k = 0; k < 8; k++) v[k] = sh[phi(k * 512 + t)];
        __syncthreads();
        RADIX8;
        #pragma unroll
        for (int k = 0; k < 8; k++) sh[phi(t * 8 + k)] = v[k];
        __syncthreads();
    }

    #pragma unroll
    for (int k = 0; k < 8; k++) v[k] = sh[phi(k * 512 + t)];
    RADIX8;                                            // logical bits 0..2
    // logical index = 8t+k -> 64B contiguous per thread, STG.128 x4
    float4* out4 = (float4*)&g_circ[base + t * 8];
    #pragma unroll
    for (int k = 0; k < 4; k++)
        out4[k] = make_float4(v[2*k].x, v[2*k].y, v[2*k+1].x, v[2*k+1].y);
}

// ---------------------------------------------------------------------------
// Kernel B: 10 butterfly stages over the high 10 bits (row index j, stride
// 4096). Block tile = 4 low columns x 1024 rows. Same rotation scheme on the
// 12-bit key (j*4 + l): rounds process j bits {7..9},{4..6},{1..3},{0}.
// First round fused with the (32B-sector coalesced) global row load; final
// single stage fused with the epilogue.
// LAST=false: fuse next layer's cost phase exp(i*gamma[layer+1]*h) on store.
// LAST=true : fuse the final sum(|c|^2 * hS) reduction (no store-back).
// ---------------------------------------------------------------------------
template <bool LAST>
__global__ void __launch_bounds__(THREADS)
kernelB(const float* __restrict__ h,
        const float* __restrict__ hS,
        const float* __restrict__ gamma,
        const float* __restrict__ beta,
        int layer)
{
    __shared__ float2 sh[4096];   // 32 KB

    const int t       = threadIdx.x;
    const int lowbase = blockIdx.x << 2;
    const int l  = t & 3;
    const int jb = t >> 2;
    const float cb = cosf(beta[layer]);
    const float sb = sinf(beta[layer]);
    float2 v[8];

    // Fused load + first round: j = jb + k*128 -> key = t + k*512,
    // key bits 9..11 = k = j bits 7..9 (butterfly bits). 32B sectors.
    #pragma unroll
    for (int k = 0; k < 8; k++)
        v[k] = g_circ[((jb + k * 128) << 12) + lowbase + l];
    RADIX8;                                            // j bits 7..9
    #pragma unroll
    for (int k = 0; k < 8; k++) sh[phi(t * 8 + k)] = v[k];
    __syncthreads();

    #pragma unroll
    for (int r = 0; r < 2; r++) {                      // j bits 4..6, then 1..3
        #pragma unroll
        for (int k = 0; k < 8; k++) v[k] = sh[phi(k * 512 + t)];
        __syncthreads();
        RADIX8;
        #pragma unroll
        for (int k = 0; k < 8; k++) sh[phi(t * 8 + k)] = v[k];
        __syncthreads();
    }

    // Final round: k bits = (l0, l1, j0) -> butterfly on bit2 of k only.
    #pragma unroll
    for (int k = 0; k < 8; k++) v[k] = sh[phi(k * 512 + t)];
    BF(0,4) BF(1,5) BF(2,6) BF(3,7)                    // j bit 0

    // logical = 8t+k -> j = 2t + (k>>2), column = k&3 (two 32B rows/thread)
    if (!LAST) {
        const float g1 = gamma[layer + 1];
        #pragma unroll
        for (int k = 0; k < 8; k++) {
            int j    = 2 * t + (k >> 2);
            int gidx = (j << 12) + lowbase + (k & 3);
            float sp, cp;
            __sincosf(g1 * h[gidx], &sp, &cp);
            g_circ[gidx] = make_float2(v[k].x * cp - v[k].y * sp,
                                       v[k].x * sp + v[k].y * cp);
        }
    } else {
        double acc = 0.0;
        #pragma unroll
        for (int k = 0; k < 8; k++) {
            int j    = 2 * t + (k >> 2);
            int gidx = (j << 12) + lowbase + (k & 3);
            float p  = fmaf(v[k].x, v[k].x, v[k].y * v[k].y);
            acc += (double)p * (double)hS[gidx];
        }
        #pragma unroll
        for (int o = 16; o > 0; o >>= 1)
            acc += __shfl_down_sync(0xffffffffu, acc, o);
        __shared__ double warpsum[THREADS / 32];
        if ((t & 31) == 0) warpsum[t >> 5] = acc;
        __syncthreads();
        if (t < THREADS / 32) {
            acc = warpsum[t];
            #pragma unroll
            for (int o = (THREADS / 64); o > 0; o >>= 1)
                acc += __shfl_down_sync(0xffffu, acc, o);
            if (t == 0) atomicAdd(&g_sum, acc);
        }
    }
}

extern "C" void kernel_launch(void* const* d_in, const int* in_sizes, int n_in,
                              void* d_out, int out_size)
{
    const float* h     = (const float*)d_in[0];
    const float* hS    = (const float*)d_in[1];
    const float* gamma = (const float*)d_in[2];
    const float* beta  = (const float*)d_in[3];
    float* out = (float*)d_out;

    const int gridA = 1024;   // NSTATES / 4096
    const int gridB = 1024;   // 4096 low indices / 4 per tile

    // Layer 0: init + phase(gamma0) + 12 low-bit stages (also zeroes g_sum)
    kernelA<true><<<gridA, THREADS>>>(h, gamma, beta, 0);
    // Layer 0: 10 high-bit stages + fused phase(gamma1)
    kernelB<false><<<gridB, THREADS>>>(h, hS, gamma, beta, 0);
    // Layer 1: 12 low-bit stages
    kernelA<false><<<gridA, THREADS>>>(h, gamma, beta, 1);
    // Layer 1: 10 high-bit stages + fused |c|^2 * hS reduction
    kernelB<true><<<gridB, THREADS>>>(h, hS, gamma, beta, 1);

    finalize_kernel<<<1, 1>>>(out);
}

// round 10
// speedup vs baseline: 1.4824x; 1.0329x over previous
#include <cuda_runtime.h>
#include <math.h>

#define NSTATES (1 << 22)      // 4,194,304 amplitudes
#define THREADS 512

// Scratch statevector (32 MB) and reduction accumulator as device globals.
__device__ float2 g_circ[NSTATES];
__device__ double g_sum;

__global__ void finalize_kernel(float* out) { out[0] = (float)g_sum; }

// Bank-conflict-free smem address swizzle. With this mapping, both access
// patterns used below (read a=k*512+t, write a=8t+k) are verified
// conflict-free for 64-bit LDS/STS across every 16-lane phase.
__device__ __forceinline__ int phi(int a) {
    return a ^ (((a >> 3) ^ (a >> 6)) & 7);
}

// One Rx-mixing butterfly on registers A,C:
//   A' = cb*A + i*sb*C ;  C' = cb*C + i*sb*A
#define BF(A, C) { float ax=v[A].x, ay=v[A].y, cx=v[C].x, cy=v[C].y; \
    v[A].x = fmaf(cb, ax, -sb * cy); v[A].y = fmaf(cb, ay,  sb * cx); \
    v[C].x = fmaf(cb, cx, -sb * ay); v[C].y = fmaf(cb, cy,  sb * ax); }

// 3 butterfly stages on the 3 k-bits of v[0..7]
#define RADIX8 { BF(0,1) BF(2,3) BF(4,5) BF(6,7) \
                 BF(0,2) BF(1,3) BF(4,6) BF(5,7) \
                 BF(0,4) BF(1,5) BF(2,6) BF(3,7) }

// ---------------------------------------------------------------------------
// Kernel A: 12 butterfly stages over the low 12 bits, block = 4096 contiguous
// amplitudes. 4 register-radix-8 rounds (3 stages each); between rounds the
// storage key rotates left by 3 bits so every round reads k*512+t and writes
// 8t+k (both conflict-free under phi). First round fused with global load,
// last round fused with global store (64B contiguous per thread).
// __launch_bounds__(512,3): cap regs at 42 so 3 CTAs (48 warps) fit per SM.
// INIT=true: synthesize (1/2048)*exp(i*gamma0*h) in-register; also zero g_sum.
// ---------------------------------------------------------------------------
template <bool INIT>
__global__ void __launch_bounds__(THREADS, 3)
kernelA(const float* __restrict__ h,
        const float* __restrict__ gamma,
        const float* __restrict__ beta,
        int layer)
{
    __shared__ float2 sh[4096];   // 32 KB; 3 CTAs -> 96 KB of 228 KB

    const int t    = threadIdx.x;
    const int base = blockIdx.x << 12;
    const float cb = cosf(beta[layer]);
    const float sb = sinf(beta[layer]);
    float2 v[8];

    if (INIT) {
        if (blockIdx.x == 0 && t == 0) g_sum = 0.0;   // stream-ordered zero
        const float s  = 1.0f / 2048.0f;               // 1/sqrt(2^22)
        const float g0 = gamma[0];
        #pragma unroll
        for (int k = 0; k < 8; k++) {                  // coalesced: 128B/warp
            float sp, cp;
            __sincosf(g0 * h[base + k * 512 + t], &sp, &cp);
            v[k] = make_float2(s * cp, s * sp);
        }
    } else {
        #pragma unroll
        for (int k = 0; k < 8; k++)                    // coalesced: 256B/warp
            v[k] = g_circ[base + k * 512 + t];
    }
    RADIX8;                                            // logical bits 9..11
    #pragma unroll
    for (int k = 0; k < 8; k++) sh[phi(t * 8 + k)] = v[k];
    __syncthreads();

    #pragma unroll
    for (int r = 0; r < 2; r++) {                      // bits 6..8, then 3..5
        #pragma unroll
        for (int k = 0; k < 8; k++) v[k] = sh[phi(k * 512 + t)];
        __syncthreads();
        RADIX8;
        #pragma unroll
        for (int k = 0; k < 8; k++) sh[phi(t * 8 + k)] = v[k];
        __syncthreads();
    }

    #pragma unroll
    for (int k = 0; k < 8; k++) v[k] = sh[phi(k * 512 + t)];
    RADIX8;                                            // logical bits 0..2
    // logical index = 8t+k -> 64B contiguous per thread, STG.128 x4
    float4* out4 = (float4*)&g_circ[base + t * 8];
    #pragma unroll
    for (int k = 0; k < 4; k++)
        out4[k] = make_float4(v[2*k].x, v[2*k].y, v[2*k+1].x, v[2*k+1].y);
}

// ---------------------------------------------------------------------------
// Kernel B: 10 butterfly stages over the high 10 bits (row index j, stride
// 4096). Block tile = 4 low columns x 1024 rows. Same rotation scheme on the
// 12-bit key (j*4 + l): rounds process j bits {7..9},{4..6},{1..3},{0}.
// First round fused with the (32B-sector coalesced) global row load; final
// single stage fused with the epilogue.
// __launch_bounds__(512,3): cap regs at 42 so 3 CTAs (48 warps) fit per SM.
// LAST=false: fuse next layer's cost phase exp(i*gamma[layer+1]*h) on store.
// LAST=true : fuse the final sum(|c|^2 * hS) reduction (no store-back).
// ---------------------------------------------------------------------------
template <bool LAST>
__global__ void __launch_bounds__(THREADS, 3)
kernelB(const float* __restrict__ h,
        const float* __restrict__ hS,
        const float* __restrict__ gamma,
        const float* __restrict__ beta,
        int layer)
{
    __shared__ float2 sh[4096];   // 32 KB

    const int t       = threadIdx.x;
    const int lowbase = blockIdx.x << 2;
    const int l  = t & 3;
    const int jb = t >> 2;
    const float cb = cosf(beta[layer]);
    const float sb = sinf(beta[layer]);
    float2 v[8];

    // Fused load + first round: j = jb + k*128 -> key = t + k*512,
    // key bits 9..11 = k = j bits 7..9 (butterfly bits). 32B sectors.
    #pragma unroll
    for (int k = 0; k < 8; k++)
        v[k] = g_circ[((jb + k * 128) << 12) + lowbase + l];
    RADIX8;                                            // j bits 7..9
    #pragma unroll
    for (int k = 0; k < 8; k++) sh[phi(t * 8 + k)] = v[k];
    __syncthreads();

    #pragma unroll
    for (int r = 0; r < 2; r++) {                      // j bits 4..6, then 1..3
        #pragma unroll
        for (int k = 0; k < 8; k++) v[k] = sh[phi(k * 512 + t)];
        __syncthreads();
        RADIX8;
        #pragma unroll
        for (int k = 0; k < 8; k++) sh[phi(t * 8 + k)] = v[k];
        __syncthreads();
    }

    // Final round: k bits = (l0, l1, j0) -> butterfly on bit2 of k only.
    #pragma unroll
    for (int k = 0; k < 8; k++) v[k] = sh[phi(k * 512 + t)];
    BF(0,4) BF(1,5) BF(2,6) BF(3,7)                    // j bit 0

    // logical = 8t+k -> j = 2t + (k>>2), column = k&3 (two 32B rows/thread)
    if (!LAST) {
        const float g1 = gamma[layer + 1];
        #pragma unroll
        for (int k = 0; k < 8; k++) {
            int j    = 2 * t + (k >> 2);
            int gidx = (j << 12) + lowbase + (k & 3);
            float sp, cp;
            __sincosf(g1 * h[gidx], &sp, &cp);
            g_circ[gidx] = make_float2(v[k].x * cp - v[k].y * sp,
                                       v[k].x * sp + v[k].y * cp);
        }
    } else {
        double acc = 0.0;
        #pragma unroll
        for (int k = 0; k < 8; k++) {
            int j    = 2 * t + (k >> 2);
            int gidx = (j << 12) + lowbase + (k & 3);
            float p  = fmaf(v[k].x, v[k].x, v[k].y * v[k].y);
            acc += (double)p * (double)hS[gidx];
        }
        #pragma unroll
        for (int o = 16; o > 0; o >>= 1)
            acc += __shfl_down_sync(0xffffffffu, acc, o);
        __shared__ double warpsum[THREADS / 32];
        if ((t & 31) == 0) warpsum[t >> 5] = acc;
        __syncthreads();
        if (t < THREADS / 32) {
            acc = warpsum[t];
            #pragma unroll
            for (int o = (THREADS / 64); o > 0; o >>= 1)
                acc += __shfl_down_sync(0xffffu, acc, o);
            if (t == 0) atomicAdd(&g_sum, acc);
        }
    }
}

extern "C" void kernel_launch(void* const* d_in, const int* in_sizes, int n_in,
                              void* d_out, int out_size)
{
    const float* h     = (const float*)d_in[0];
    const float* hS    = (const float*)d_in[1];
    const float* gamma = (const float*)d_in[2];
    const float* beta  = (const float*)d_in[3];
    float* out = (float*)d_out;

    const int gridA = 1024;   // NSTATES / 4096
    const int gridB = 1024;   // 4096 low indices / 4 per tile

    // Layer 0: init + phase(gamma0) + 12 low-bit stages (also zeroes g_sum)
    kernelA<true><<<gridA, THREADS>>>(h, gamma, beta, 0);
    // Layer 0: 10 high-bit stages + fused phase(gamma1)
    kernelB<false><<<gridB, THREADS>>>(h, hS, gamma, beta, 0);
    // Layer 1: 12 low-bit stages
    kernelA<false><<<gridA, THREADS>>>(h, gamma, beta, 1);
    // Layer 1: 10 high-bit stages + fused |c|^2 * hS reduction
    kernelB<true><<<gridB, THREADS>>>(h, hS, gamma, beta, 1);

    finalize_kernel<<<1, 1>>>(out);
}

// round 11
// speedup vs baseline: 1.5605x; 1.0527x over previous
#include <cuda_runtime.h>
#include <math.h>

#define NSTATES (1 << 22)      // 4,194,304 amplitudes
#define THREADS 128            // 32 complex per thread (radix-32)

// Scratch statevector (32 MB) and reduction accumulator as device globals.
__device__ float2 g_circ[NSTATES];
__device__ double g_sum;

__global__ void finalize_kernel(float* out) { out[0] = (float)g_sum; }

// Bank-conflict-free smem swizzle for the radix-32 patterns:
//   write a = t*32 + k : bank8 = (k ^ lane) & 15      -> distinct per phase
//   read  a = k*128 + t: bank8 = (lane ^ const) & 15  -> distinct per phase
__device__ __forceinline__ int phi(int a) {
    return a ^ ((a >> 5) & 15);
}

// One butterfly stage of distance d over the 5 register-index bits of v[0..32)
__device__ __forceinline__ void stage32(float2* v, const int d,
                                        const float cb, const float sb) {
    #pragma unroll
    for (int m = 0; m < 32; m++) if (!(m & d)) {
        float ax = v[m].x,     ay = v[m].y;
        float cx = v[m | d].x, cy = v[m | d].y;
        v[m].x     = fmaf(cb, ax, -sb * cy);
        v[m].y     = fmaf(cb, ay,  sb * cx);
        v[m | d].x = fmaf(cb, cx, -sb * ay);
        v[m | d].y = fmaf(cb, cy,  sb * ax);
    }
}
#define RADIX32(v) { stage32(v,1,cb,sb);  stage32(v,2,cb,sb); \
                     stage32(v,4,cb,sb);  stage32(v,8,cb,sb); \
                     stage32(v,16,cb,sb); }

// ---------------------------------------------------------------------------
// Kernel A: 12 butterfly stages over the low 12 bits; block = 4096 contiguous
// amplitudes, 128 threads x 32 complex in registers. Rounds 5+5+2 with the
// rotl5 storage relabeling: every round reads smem at k*128+t and writes at
// t*32+k (both conflict-free under phi). Two smem round-trips, 3 barriers.
//  round 1 (fused global load): logical bits 7..11
//  round 2:                     logical bits 2..6
//  round 3 (fused store):       logical bits 0..1 (register bits 3,4)
// Final store: logical = (k&7)*512 + t*4 + (k>>3) -> float4 pairs, 1KB/warp.
// INIT=true: synthesize (1/2048)*exp(i*gamma0*h) in-register; zero g_sum.
// ---------------------------------------------------------------------------
template <bool INIT>
__global__ void __launch_bounds__(THREADS, 4)
kernelA(const float* __restrict__ h,
        const float* __restrict__ gamma,
        const float* __restrict__ beta,
        int layer)
{
    __shared__ float2 sh[4096];   // 32 KB

    const int t    = threadIdx.x;
    const int base = blockIdx.x << 12;
    const float cb = cosf(beta[layer]);
    const float sb = sinf(beta[layer]);
    float2 v[32];

    if (INIT) {
        if (blockIdx.x == 0 && t == 0) g_sum = 0.0;   // stream-ordered zero
        const float s  = 1.0f / 2048.0f;               // 1/sqrt(2^22)
        const float g0 = gamma[0];
        #pragma unroll
        for (int k = 0; k < 32; k++) {                 // 256B/warp coalesced
            float sp, cp;
            __sincosf(g0 * h[base + k * 128 + t], &sp, &cp);
            v[k] = make_float2(s * cp, s * sp);
        }
    } else {
        #pragma unroll
        for (int k = 0; k < 32; k++)
            v[k] = g_circ[base + k * 128 + t];
    }
    RADIX32(v);                                        // logical bits 7..11

    #pragma unroll
    for (int k = 0; k < 32; k++) sh[phi(t * 32 + k)] = v[k];
    __syncthreads();
    #pragma unroll
    for (int k = 0; k < 32; k++) v[k] = sh[phi(k * 128 + t)];
    RADIX32(v);                                        // logical bits 2..6
    __syncthreads();

    #pragma unroll
    for (int k = 0; k < 32; k++) sh[phi(t * 32 + k)] = v[k];
    __syncthreads();
    #pragma unroll
    for (int k = 0; k < 32; k++) v[k] = sh[phi(k * 128 + t)];
    stage32(v, 8,  cb, sb);                            // logical bit 0
    stage32(v, 16, cb, sb);                            // logical bit 1

    // logical = (k&7)*512 + t*4 + (k>>3): 4 consecutive elems per (c)
    #pragma unroll
    for (int c = 0; c < 8; c++) {
        float4* o = (float4*)&g_circ[base + c * 512 + t * 4];
        o[0] = make_float4(v[c].x,      v[c].y,      v[c + 8].x,  v[c + 8].y);
        o[1] = make_float4(v[c + 16].x, v[c + 16].y, v[c + 24].x, v[c + 24].y);
    }
}

// ---------------------------------------------------------------------------
// Kernel B: 10 butterfly stages over the high 10 bits (row j, stride 4096).
// Tile = 4 low columns x 1024 rows; 128 threads x 32 complex. Rounds 5+5:
//  round 1 (fused global load): j bits 5..9   (j = k*32 + (t>>2), l = t&3)
//  round 2 (fused epilogue):    j bits 0..4   (j = (t&31)*32 + k, l = t>>5)
// ONE smem round-trip, ONE barrier.
// LAST=false: fuse next layer's cost phase exp(i*gamma[layer+1]*h) on store.
// LAST=true : fuse the final sum(|c|^2 * hS) reduction (no store-back).
// ---------------------------------------------------------------------------
template <bool LAST>
__global__ void __launch_bounds__(THREADS, 4)
kernelB(const float* __restrict__ h,
        const float* __restrict__ hS,
        const float* __restrict__ gamma,
        const float* __restrict__ beta,
        int layer)
{
    __shared__ float2 sh[4096];   // 32 KB

    const int t       = threadIdx.x;
    const int lowbase = blockIdx.x << 2;
    const float cb = cosf(beta[layer]);
    const float sb = sinf(beta[layer]);
    float2 v[32];

    // Fused load + round 1: storage key = k*128 + t, j = k*32 + (t>>2).
    #pragma unroll
    for (int k = 0; k < 32; k++)
        v[k] = g_circ[((k * 32 + (t >> 2)) << 12) + lowbase + (t & 3)];
    RADIX32(v);                                        // j bits 5..9

    #pragma unroll
    for (int k = 0; k < 32; k++) sh[phi(t * 32 + k)] = v[k];
    __syncthreads();
    #pragma unroll
    for (int k = 0; k < 32; k++) v[k] = sh[phi(k * 128 + t)];
    RADIX32(v);                                        // j bits 0..4

    // Epilogue coordinates: j = (t&31)*32 + k, column = t>>5.
    const int tl = t & 31;
    const int w  = t >> 5;
    if (!LAST) {
        const float g1 = gamma[layer + 1];
        #pragma unroll
        for (int k = 0; k < 32; k++) {
            int gidx = ((tl * 32 + k) << 12) + lowbase + w;
            float sp, cp;
            __sincosf(g1 * h[gidx], &sp, &cp);
            g_circ[gidx] = make_float2(v[k].x * cp - v[k].y * sp,
                                       v[k].x * sp + v[k].y * cp);
        }
    } else {
        double a0 = 0.0, a1 = 0.0, a2 = 0.0, a3 = 0.0;  // break DFMA chain
        #pragma unroll
        for (int k = 0; k < 32; k += 4) {
            int g0i = ((tl * 32 + k    ) << 12) + lowbase + w;
            int g1i = ((tl * 32 + k + 1) << 12) + lowbase + w;
            int g2i = ((tl * 32 + k + 2) << 12) + lowbase + w;
            int g3i = ((tl * 32 + k + 3) << 12) + lowbase + w;
            a0 += (double)fmaf(v[k  ].x, v[k  ].x, v[k  ].y * v[k  ].y) * (double)hS[g0i];
            a1 += (double)fmaf(v[k+1].x, v[k+1].x, v[k+1].y * v[k+1].y) * (double)hS[g1i];
            a2 += (double)fmaf(v[k+2].x, v[k+2].x, v[k+2].y * v[k+2].y) * (double)hS[g2i];
            a3 += (double)fmaf(v[k+3].x, v[k+3].x, v[k+3].y * v[k+3].y) * (double)hS[g3i];
        }
        double acc = (a0 + a1) + (a2 + a3);
        #pragma unroll
        for (int o = 16; o > 0; o >>= 1)
            acc += __shfl_down_sync(0xffffffffu, acc, o);
        __shared__ double wsum[4];
        if ((t & 31) == 0) wsum[w] = acc;
        __syncthreads();
        if (t == 0)
            atomicAdd(&g_sum, (wsum[0] + wsum[1]) + (wsum[2] + wsum[3]));
    }
}

extern "C" void kernel_launch(void* const* d_in, const int* in_sizes, int n_in,
                              void* d_out, int out_size)
{
    const float* h     = (const float*)d_in[0];
    const float* hS    = (const float*)d_in[1];
    const float* gamma = (const float*)d_in[2];
    const float* beta  = (const float*)d_in[3];
    float* out = (float*)d_out;

    const int gridA = 1024;   // NSTATES / 4096
    const int gridB = 1024;   // 4096 low indices / 4 per tile

    // Layer 0: init + phase(gamma0) + 12 low-bit stages (also zeroes g_sum)
    kernelA<true><<<gridA, THREADS>>>(h, gamma, beta, 0);
    // Layer 0: 10 high-bit stages + fused phase(gamma1)
    kernelB<false><<<gridB, THREADS>>>(h, hS, gamma, beta, 0);
    // Layer 1: 12 low-bit stages
    kernelA<false><<<gridA, THREADS>>>(h, gamma, beta, 1);
    // Layer 1: 10 high-bit stages + fused |c|^2 * hS reduction
    kernelB<true><<<gridB, THREADS>>>(h, hS, gamma, beta, 1);

    finalize_kernel<<<1, 1>>>(out);
}

// round 12
// speedup vs baseline: 2.7600x; 1.7687x over previous
#include <cuda_runtime.h>
#include <math.h>

#define NSTATES (1 << 22)      // 4,194,304 amplitudes
#define ATHREADS 128           // kernelA: 32 complex per thread
#define BTHREADS 256           // kernelB: 32 complex per thread

// Scratch statevector (32 MB) and reduction accumulator as device globals.
__device__ float2 g_circ[NSTATES];
__device__ double g_sum;

__global__ void finalize_kernel(float* out) { out[0] = (float)g_sum; }

// kernelA swizzle (radix-32, 128-thread patterns) — verified conflict-free.
__device__ __forceinline__ int phi(int a) {
    return a ^ ((a >> 5) & 15);
}
// kernelB state swizzle (float2 units): flip bit3 by j-bit5 (addr bit 8).
__device__ __forceinline__ int phiS(int a) {
    return a ^ (((a >> 8) & 1) << 3);
}

// One butterfly stage of distance d over the 5 register-index bits of v[0..32)
__device__ __forceinline__ void stage32(float2* v, const int d,
                                        const float cb, const float sb) {
    #pragma unroll
    for (int m = 0; m < 32; m++) if (!(m & d)) {
        float ax = v[m].x,     ay = v[m].y;
        float cx = v[m | d].x, cy = v[m | d].y;
        v[m].x     = fmaf(cb, ax, -sb * cy);
        v[m].y     = fmaf(cb, ay,  sb * cx);
        v[m | d].x = fmaf(cb, cx, -sb * ay);
        v[m | d].y = fmaf(cb, cy,  sb * ax);
    }
}
#define RADIX32(v) { stage32(v,1,cb,sb);  stage32(v,2,cb,sb); \
                     stage32(v,4,cb,sb);  stage32(v,8,cb,sb); \
                     stage32(v,16,cb,sb); }

// ---------------------------------------------------------------------------
// Kernel A (unchanged from R11): 12 stages over the low 12 bits; block = 4096
// contiguous amplitudes, 128 threads x 32 complex. Rounds 5+5+2, rotl5
// relabeling, two smem round-trips, 3 barriers.
// INIT=true: synthesize (1/2048)*exp(i*gamma0*h) in-register; zero g_sum.
// ---------------------------------------------------------------------------
template <bool INIT>
__global__ void __launch_bounds__(ATHREADS, 4)
kernelA(const float* __restrict__ h,
        const float* __restrict__ gamma,
        const float* __restrict__ beta,
        int layer)
{
    __shared__ float2 sh[4096];   // 32 KB

    const int t    = threadIdx.x;
    const int base = blockIdx.x << 12;
    const float cb = cosf(beta[layer]);
    const float sb = sinf(beta[layer]);
    float2 v[32];

    if (INIT) {
        if (blockIdx.x == 0 && t == 0) g_sum = 0.0;   // stream-ordered zero
        const float s  = 1.0f / 2048.0f;               // 1/sqrt(2^22)
        const float g0 = gamma[0];
        #pragma unroll
        for (int k = 0; k < 32; k++) {
            float sp, cp;
            __sincosf(g0 * h[base + k * 128 + t], &sp, &cp);
            v[k] = make_float2(s * cp, s * sp);
        }
    } else {
        #pragma unroll
        for (int k = 0; k < 32; k++)
            v[k] = g_circ[base + k * 128 + t];
    }
    RADIX32(v);                                        // logical bits 7..11

    #pragma unroll
    for (int k = 0; k < 32; k++) sh[phi(t * 32 + k)] = v[k];
    __syncthreads();
    #pragma unroll
    for (int k = 0; k < 32; k++) v[k] = sh[phi(k * 128 + t)];
    RADIX32(v);                                        // logical bits 2..6
    __syncthreads();

    #pragma unroll
    for (int k = 0; k < 32; k++) sh[phi(t * 32 + k)] = v[k];
    __syncthreads();
    #pragma unroll
    for (int k = 0; k < 32; k++) v[k] = sh[phi(k * 128 + t)];
    stage32(v, 8,  cb, sb);                            // logical bit 0
    stage32(v, 16, cb, sb);                            // logical bit 1

    // logical = (k&7)*512 + t*4 + (k>>3): float4 pairs, 1KB/warp contiguous
    #pragma unroll
    for (int c = 0; c < 8; c++) {
        float4* o = (float4*)&g_circ[base + c * 512 + t * 4];
        o[0] = make_float4(v[c].x,      v[c].y,      v[c + 8].x,  v[c + 8].y);
        o[1] = make_float4(v[c + 16].x, v[c + 16].y, v[c + 24].x, v[c + 24].y);
    }
}

// ---------------------------------------------------------------------------
// Kernel B v3: 10 stages over the high 10 bits (row j, stride 4096).
// Tile = 8 low columns x 1024 rows (8192 float2 = 64 KB DYNAMIC smem),
// 256 threads x 32 complex, 2 CTAs/SM. Thread t: column l = t&7,
// j-group jb = t>>3 (0..31). Rounds 5+5, ONE barrier:
//  round 1 (fused global load, 64B/8 lanes): j = k*32 + jb  (j bits 5..9)
//  round 2 (fused epilogue):                 j = jb*32 + k  (j bits 0..4)
// smem: addr = j*8 + l under phiS; round-1 STS at k*256+t (linear),
// round-2 LDS at jb*256 + k*8 + l. Both bank-exact conflict-free.
// LAST=false: fuse next layer's cost phase exp(i*gamma[layer+1]*h) on store.
// LAST=true : fuse the final sum(|c|^2 * hS) reduction (no store-back).
// ---------------------------------------------------------------------------
template <bool LAST>
__global__ void __launch_bounds__(BTHREADS, 2)
kernelB(const float* __restrict__ h,
        const float* __restrict__ hS,
        const float* __restrict__ gamma,
        const float* __restrict__ beta,
        int layer)
{
    extern __shared__ float2 sst[];   // 8192 float2 = 64 KB dynamic

    const int t       = threadIdx.x;
    const int l       = t & 7;
    const int jb      = t >> 3;          // 0..31
    const int lowbase = blockIdx.x << 3;
    const float cb = cosf(beta[layer]);
    const float sb = sinf(beta[layer]);
    float2 v[32];

    // Fused load + round 1: j = k*32 + jb. 8 lanes cover 64B contiguous.
    #pragma unroll
    for (int k = 0; k < 32; k++)
        v[k] = g_circ[((k * 32 + jb) << 12) + lowbase + l];
    RADIX32(v);                                        // j bits 5..9

    #pragma unroll
    for (int k = 0; k < 32; k++) sst[phiS(k * 256 + t)] = v[k];
    __syncthreads();
    #pragma unroll
    for (int k = 0; k < 32; k++) v[k] = sst[phiS(jb * 256 + k * 8 + l)];
    RADIX32(v);                                        // j bits 0..4

    // Epilogue: thread holds j = jb*32 + k, column l. 8 lanes contiguous.
    if (!LAST) {
        const float g1 = gamma[layer + 1];
        #pragma unroll
        for (int k = 0; k < 32; k++) {
            int gidx = ((jb * 32 + k) << 12) + lowbase + l;
            float sp, cp;
            __sincosf(g1 * h[gidx], &sp, &cp);
            g_circ[gidx] = make_float2(v[k].x * cp - v[k].y * sp,
                                       v[k].x * sp + v[k].y * cp);
        }
    } else {
        float f0 = 0.0f, f1 = 0.0f;     // two float accumulators (32 terms)
        #pragma unroll
        for (int k = 0; k < 32; k += 2) {
            int gi0 = ((jb * 32 + k    ) << 12) + lowbase + l;
            int gi1 = ((jb * 32 + k + 1) << 12) + lowbase + l;
            f0 = fmaf(fmaf(v[k  ].x, v[k  ].x, v[k  ].y * v[k  ].y), hS[gi0], f0);
            f1 = fmaf(fmaf(v[k+1].x, v[k+1].x, v[k+1].y * v[k+1].y), hS[gi1], f1);
        }
        double acc = (double)f0 + (double)f1;
        #pragma unroll
        for (int o = 16; o > 0; o >>= 1)
            acc += __shfl_down_sync(0xffffffffu, acc, o);
        __shared__ double wsum[BTHREADS / 32];
        if ((t & 31) == 0) wsum[t >> 5] = acc;
        __syncthreads();
        if (t < 32) {
            double a = (t < BTHREADS / 32) ? wsum[t] : 0.0;
            #pragma unroll
            for (int o = 4; o > 0; o >>= 1)
                a += __shfl_down_sync(0xffffffffu, a, o);
            if (t == 0) atomicAdd(&g_sum, a);
        }
    }
}

extern "C" void kernel_launch(void* const* d_in, const int* in_sizes, int n_in,
                              void* d_out, int out_size)
{
    const float* h     = (const float*)d_in[0];
    const float* hS    = (const float*)d_in[1];
    const float* gamma = (const float*)d_in[2];
    const float* beta  = (const float*)d_in[3];
    float* out = (float*)d_out;

    const int smemB = 8192 * sizeof(float2);   // 64 KB dynamic
    cudaFuncSetAttribute((const void*)kernelB<false>,
                         cudaFuncAttributeMaxDynamicSharedMemorySize, smemB);
    cudaFuncSetAttribute((const void*)kernelB<true>,
                         cudaFuncAttributeMaxDynamicSharedMemorySize, smemB);

    const int gridA = 1024;   // NSTATES / 4096
    const int gridB = 512;    // 4096 low indices / 8 per tile

    // Layer 0: init + phase(gamma0) + 12 low-bit stages (also zeroes g_sum)
    kernelA<true><<<gridA, ATHREADS>>>(h, gamma, beta, 0);
    // Layer 0: 10 high-bit stages + fused phase(gamma1)
    kernelB<false><<<gridB, BTHREADS, smemB>>>(h, hS, gamma, beta, 0);
    // Layer 1: 12 low-bit stages
    kernelA<false><<<gridA, ATHREADS>>>(h, gamma, beta, 1);
    // Layer 1: 10 high-bit stages + fused |c|^2 * hS reduction
    kernelB<true><<<gridB, BTHREADS, smemB>>>(h, hS, gamma, beta, 1);

    finalize_kernel<<<1, 1>>>(out);
}

// round 13
// speedup vs baseline: 3.2644x; 1.1828x over previous
#include <cuda_runtime.h>
#include <math.h>

#define NSTATES (1 << 22)      // 4,194,304 amplitudes
#define ATHREADS 128           // kernelA: 32 complex per thread
#define BTHREADS 256           // kernelBmid: 32 complex per thread

// Scratch statevector (32 MB) and reduction accumulator as device globals.
__device__ float2 g_circ[NSTATES];
__device__ double g_sum;

__global__ void finalize_kernel(float* out) { out[0] = (float)g_sum; }

// kernelA swizzle (radix-32, 128-thread patterns) — verified conflict-free.
__device__ __forceinline__ int phi(int a) {
    return a ^ ((a >> 5) & 15);
}
// kernelB state swizzle (float2 units): flip bit3 by j-bit5 (addr bit 8).
__device__ __forceinline__ int phiS(int a) {
    return a ^ (((a >> 8) & 1) << 3);
}
// kernelB h-tile swizzle (float units): spread jb across bank octets.
__device__ __forceinline__ int phiH(int a) {
    return a ^ (((a >> 8) & 3) << 3);
}

// One butterfly stage of distance d over the 5 register-index bits of v[0..32)
__device__ __forceinline__ void stage32(float2* v, const int d,
                                        const float cb, const float sb) {
    #pragma unroll
    for (int m = 0; m < 32; m++) if (!(m & d)) {
        float ax = v[m].x,     ay = v[m].y;
        float cx = v[m | d].x, cy = v[m | d].y;
        v[m].x     = fmaf(cb, ax, -sb * cy);
        v[m].y     = fmaf(cb, ay,  sb * cx);
        v[m | d].x = fmaf(cb, cx, -sb * ay);
        v[m | d].y = fmaf(cb, cy,  sb * ax);
    }
}
#define RADIX32(v, CB, SB) { stage32(v,1,CB,SB);  stage32(v,2,CB,SB);  \
                             stage32(v,4,CB,SB);  stage32(v,8,CB,SB);  \
                             stage32(v,16,CB,SB); }

// ---------------------------------------------------------------------------
// Kernel A_init: layer-0 phase + 12 stages over the low 12 bits; block = 4096
// contiguous amplitudes, 128 threads x 32 complex. Rounds 5+5+2 with the
// rotl5 storage relabeling. Synthesizes (1/2048)*exp(i*gamma0*h) in-register;
// also zeroes g_sum (stream-ordered).
// ---------------------------------------------------------------------------
__global__ void __launch_bounds__(ATHREADS, 4)
kernelA_init(const float* __restrict__ h,
             const float* __restrict__ gamma,
             const float* __restrict__ beta)
{
    __shared__ float2 sh[4096];   // 32 KB

    const int t    = threadIdx.x;
    const int base = blockIdx.x << 12;
    const float cb = cosf(beta[0]);
    const float sb = sinf(beta[0]);
    float2 v[32];

    if (blockIdx.x == 0 && t == 0) g_sum = 0.0;
    {
        const float s  = 1.0f / 2048.0f;   // 1/sqrt(2^22)
        const float g0 = gamma[0];
        #pragma unroll
        for (int k = 0; k < 32; k++) {
            float sp, cp;
            __sincosf(g0 * h[base + k * 128 + t], &sp, &cp);
            v[k] = make_float2(s * cp, s * sp);
        }
    }
    RADIX32(v, cb, sb);                                // logical bits 7..11

    #pragma unroll
    for (int k = 0; k < 32; k++) sh[phi(t * 32 + k)] = v[k];
    __syncthreads();
    #pragma unroll
    for (int k = 0; k < 32; k++) v[k] = sh[phi(k * 128 + t)];
    RADIX32(v, cb, sb);                                // logical bits 2..6
    __syncthreads();

    #pragma unroll
    for (int k = 0; k < 32; k++) sh[phi(t * 32 + k)] = v[k];
    __syncthreads();
    #pragma unroll
    for (int k = 0; k < 32; k++) v[k] = sh[phi(k * 128 + t)];
    stage32(v, 8,  cb, sb);                            // logical bit 0
    stage32(v, 16, cb, sb);                            // logical bit 1

    // logical = (k&7)*512 + t*4 + (k>>3): float4 pairs, 1KB/warp contiguous
    #pragma unroll
    for (int c = 0; c < 8; c++) {
        float4* o = (float4*)&g_circ[base + c * 512 + t * 4];
        o[0] = make_float4(v[c].x,      v[c].y,      v[c + 8].x,  v[c + 8].y);
        o[1] = make_float4(v[c + 16].x, v[c + 16].y, v[c + 24].x, v[c + 24].y);
    }
}

// ---------------------------------------------------------------------------
// Kernel Bmid: all high-bit work of BOTH layers in one kernel.
// Tile = 8 low columns x 1024 rows j (stride 4096); 256 threads x 32 complex;
// 64 KB state + 32 KB h tile = 96 KB dynamic smem, 2 CTAs/SM.
//   round 1 (fused coalesced load): layer-0 mixing, j bits 5..9
//   round 2:                        layer-0 mixing, j bits 0..4
//   phase(gamma1) from the prefetched smem h tile
//   round 3 (no exchange needed):   layer-1 mixing, j bits 0..4
//   round 4 (fused coalesced store):layer-1 mixing, j bits 5..9
// smem state addr = j*8 + l under phiS (bank-exact conflict-free both ways).
// ---------------------------------------------------------------------------
__global__ void __launch_bounds__(BTHREADS, 2)
kernelBmid(const float* __restrict__ h,
           const float* __restrict__ gamma,
           const float* __restrict__ beta)
{
    extern __shared__ float2 sst[];          // [0,8192) state  (64 KB)
    float* shh = (float*)(sst + 8192);       // 8192 floats h tile (32 KB)

    const int t       = threadIdx.x;
    const int l       = t & 7;
    const int jb      = t >> 3;              // 0..31
    const int lowbase = blockIdx.x << 3;
    const float cb0 = cosf(beta[0]), sb0 = sinf(beta[0]);
    const float cb1 = cosf(beta[1]), sb1 = sinf(beta[1]);
    const float g1  = gamma[1];
    float2 v[32];

    // Coalesced state load: j = k*32 + jb (8 lanes cover 64B contiguous).
    #pragma unroll
    for (int k = 0; k < 32; k++)
        v[k] = g_circ[((k * 32 + jb) << 12) + lowbase + l];
    // Prefetch h tile (overlaps with butterfly compute below).
    #pragma unroll
    for (int m = 0; m < 32; m++) {
        int i = t + m * 256;
        shh[phiH(i)] = h[((i >> 3) << 12) + lowbase + (i & 7)];
    }

    RADIX32(v, cb0, sb0);                              // layer0: j bits 5..9

    #pragma unroll
    for (int k = 0; k < 32; k++) sst[phiS(k * 256 + t)] = v[k];
    __syncthreads();
    #pragma unroll
    for (int k = 0; k < 32; k++) v[k] = sst[phiS(jb * 256 + k * 8 + l)];
    RADIX32(v, cb0, sb0);                              // layer0: j bits 0..4

    // Layer-1 cost phase; register k = j bits 0..4, so h index = jb*32+k.
    #pragma unroll
    for (int k = 0; k < 32; k++) {
        float hv = shh[phiH(jb * 256 + k * 8 + l)];
        float sp, cp;
        __sincosf(g1 * hv, &sp, &cp);
        v[k] = make_float2(v[k].x * cp - v[k].y * sp,
                           v[k].x * sp + v[k].y * cp);
    }

    RADIX32(v, cb1, sb1);                              // layer1: j bits 0..4
    __syncthreads();                                   // drain round-2 reads
    #pragma unroll
    for (int k = 0; k < 32; k++) sst[phiS(jb * 256 + k * 8 + l)] = v[k];
    __syncthreads();
    #pragma unroll
    for (int k = 0; k < 32; k++) v[k] = sst[phiS(k * 256 + t)];
    RADIX32(v, cb1, sb1);                              // layer1: j bits 5..9

    // Coalesced store, same pattern as the load.
    #pragma unroll
    for (int k = 0; k < 32; k++)
        g_circ[((k * 32 + jb) << 12) + lowbase + l] = v[k];
}

// ---------------------------------------------------------------------------
// Kernel A_reduce: layer-1 low-12 mixing + fused sum(|c|^2 * hS); no state
// write-back. hS tile prefetched to smem at start (read back as float4).
// ---------------------------------------------------------------------------
__global__ void __launch_bounds__(ATHREADS, 4)
kernelA_reduce(const float* __restrict__ hS,
               const float* __restrict__ beta)
{
    __shared__ float2 sh[4096];     // 32 KB
    __shared__ float  hsh[4096];    // 16 KB
    __shared__ double wsum[ATHREADS / 32];

    const int t    = threadIdx.x;
    const int base = blockIdx.x << 12;
    const float cb = cosf(beta[1]);
    const float sb = sinf(beta[1]);
    float2 v[32];

    #pragma unroll
    for (int k = 0; k < 32; k++)
        v[k] = g_circ[base + k * 128 + t];
    #pragma unroll
    for (int m = 0; m < 32; m++)                       // prefetch hS tile
        hsh[t + m * 128] = hS[base + t + m * 128];

    RADIX32(v, cb, sb);                                // logical bits 7..11

    #pragma unroll
    for (int k = 0; k < 32; k++) sh[phi(t * 32 + k)] = v[k];
    __syncthreads();
    #pragma unroll
    for (int k = 0; k < 32; k++) v[k] = sh[phi(k * 128 + t)];
    RADIX32(v, cb, sb);                                // logical bits 2..6
    __syncthreads();

    #pragma unroll
    for (int k = 0; k < 32; k++) sh[phi(t * 32 + k)] = v[k];
    __syncthreads();
    #pragma unroll
    for (int k = 0; k < 32; k++) v[k] = sh[phi(k * 128 + t)];
    stage32(v, 8,  cb, sb);                            // logical bit 0
    stage32(v, 16, cb, sb);                            // logical bit 1

    // logical c*512 + t*4 + q -> v[c + 8*q]; hS from smem as float4.
    const float4* hs4 = (const float4*)hsh;
    float a0 = 0.0f, a1 = 0.0f;
    #pragma unroll
    for (int c = 0; c < 8; c++) {
        float4 s = hs4[c * 128 + t];
        a0 = fmaf(fmaf(v[c     ].x, v[c     ].x, v[c     ].y * v[c     ].y), s.x, a0);
        a1 = fmaf(fmaf(v[c +  8].x, v[c +  8].x, v[c +  8].y * v[c +  8].y), s.y, a1);
        a0 = fmaf(fmaf(v[c + 16].x, v[c + 16].x, v[c + 16].y * v[c + 16].y), s.z, a0);
        a1 = fmaf(fmaf(v[c + 24].x, v[c + 24].x, v[c + 24].y * v[c + 24].y), s.w, a1);
    }
    double acc = (double)a0 + (double)a1;
    #pragma unroll
    for (int o = 16; o > 0; o >>= 1)
        acc += __shfl_down_sync(0xffffffffu, acc, o);
    if ((t & 31) == 0) wsum[t >> 5] = acc;
    __syncthreads();
    if (t == 0)
        atomicAdd(&g_sum, (wsum[0] + wsum[1]) + (wsum[2] + wsum[3]));
}

extern "C" void kernel_launch(void* const* d_in, const int* in_sizes, int n_in,
                              void* d_out, int out_size)
{
    const float* h     = (const float*)d_in[0];
    const float* hS    = (const float*)d_in[1];
    const float* gamma = (const float*)d_in[2];
    const float* beta  = (const float*)d_in[3];
    float* out = (float*)d_out;

    const int smemB = 8192 * sizeof(float2) + 8192 * sizeof(float); // 96 KB
    cudaFuncSetAttribute((const void*)kernelBmid,
                         cudaFuncAttributeMaxDynamicSharedMemorySize, smemB);

    // Layer 0: init + phase(gamma0) + low-12 mixing (also zeroes g_sum)
    kernelA_init<<<1024, ATHREADS>>>(h, gamma, beta);
    // High-10 mixing of layer 0, phase(gamma1), high-10 mixing of layer 1
    kernelBmid<<<512, BTHREADS, smemB>>>(h, gamma, beta);
    // Layer 1: low-12 mixing + fused |c|^2 * hS reduction
    kernelA_reduce<<<1024, ATHREADS>>>(hS, beta);

    finalize_kernel<<<1, 1>>>(out);
}

// round 14
// speedup vs baseline: 3.5240x; 1.0795x over previous
#include <cuda_runtime.h>
#include <cuda_fp16.h>
#include <math.h>

#define NSTATES (1 << 22)      // 4,194,304 amplitudes
#define ATHREADS 128           // kernelA: 32 complex per thread
#define BTHREADS 256           // kernelBmid: 32 complex per thread

// Inter-kernel statevector stored as half2 (16 MB), amplitudes UNNORMALIZED
// (O(1) magnitudes); the 1/N = 2^-22 normalization is applied exactly once in
// the final reduction. Reduction accumulator + completion counter as globals.
__device__ __half2 g_circ[NSTATES];
__device__ double  g_sum;
__device__ unsigned g_count;   // zero-initialized; reset by last block each run

__device__ __forceinline__ float2 ldState(int idx) {
    return __half22float2(g_circ[idx]);
}
__device__ __forceinline__ void stState(int idx, float2 v) {
    g_circ[idx] = __float22half2_rn(v);
}

// kernelA swizzle (radix-32, 128-thread patterns) — verified conflict-free.
__device__ __forceinline__ int phi(int a) {
    return a ^ ((a >> 5) & 15);
}
// kernelB state swizzle (float2 units): flip bit3 by j-bit5 (addr bit 8).
__device__ __forceinline__ int phiS(int a) {
    return a ^ (((a >> 8) & 1) << 3);
}
// kernelB h-tile swizzle (float units): spread jb across bank octets.
__device__ __forceinline__ int phiH(int a) {
    return a ^ (((a >> 8) & 3) << 3);
}

// One butterfly stage of distance d over the 5 register-index bits of v[0..32)
__device__ __forceinline__ void stage32(float2* v, const int d,
                                        const float cb, const float sb) {
    #pragma unroll
    for (int m = 0; m < 32; m++) if (!(m & d)) {
        float ax = v[m].x,     ay = v[m].y;
        float cx = v[m | d].x, cy = v[m | d].y;
        v[m].x     = fmaf(cb, ax, -sb * cy);
        v[m].y     = fmaf(cb, ay,  sb * cx);
        v[m | d].x = fmaf(cb, cx, -sb * ay);
        v[m | d].y = fmaf(cb, cy,  sb * ax);
    }
}
#define RADIX32(v, CB, SB) { stage32(v,1,CB,SB);  stage32(v,2,CB,SB);  \
                             stage32(v,4,CB,SB);  stage32(v,8,CB,SB);  \
                             stage32(v,16,CB,SB); }

// ---------------------------------------------------------------------------
// Kernel A_init: layer-0 phase + 12 stages over the low 12 bits; block = 4096
// contiguous amplitudes, 128 threads x 32 complex. Rounds 5+5+2 with the
// rotl5 storage relabeling. Synthesizes exp(i*gamma0*h) (unnormalized) in-
// register; also zeroes g_sum (stream-ordered).
// ---------------------------------------------------------------------------
__global__ void __launch_bounds__(ATHREADS, 4)
kernelA_init(const float* __restrict__ h,
             const float* __restrict__ gamma,
             const float* __restrict__ beta)
{
    __shared__ float2 sh[4096];   // 32 KB

    const int t    = threadIdx.x;
    const int base = blockIdx.x << 12;
    const float cb = cosf(beta[0]);
    const float sb = sinf(beta[0]);
    float2 v[32];

    if (blockIdx.x == 0 && t == 0) g_sum = 0.0;
    {
        const float g0 = gamma[0];
        #pragma unroll
        for (int k = 0; k < 32; k++) {
            float sp, cp;
            __sincosf(g0 * h[base + k * 128 + t], &sp, &cp);
            v[k] = make_float2(cp, sp);                // unnormalized
        }
    }
    RADIX32(v, cb, sb);                                // logical bits 7..11

    #pragma unroll
    for (int k = 0; k < 32; k++) sh[phi(t * 32 + k)] = v[k];
    __syncthreads();
    #pragma unroll
    for (int k = 0; k < 32; k++) v[k] = sh[phi(k * 128 + t)];
    RADIX32(v, cb, sb);                                // logical bits 2..6
    __syncthreads();

    #pragma unroll
    for (int k = 0; k < 32; k++) sh[phi(t * 32 + k)] = v[k];
    __syncthreads();
    #pragma unroll
    for (int k = 0; k < 32; k++) v[k] = sh[phi(k * 128 + t)];
    stage32(v, 8,  cb, sb);                            // logical bit 0
    stage32(v, 16, cb, sb);                            // logical bit 1

    // logical = (k&7)*512 + t*4 + (k>>3): 4 half2 = 16B per (c), contiguous
    #pragma unroll
    for (int c = 0; c < 8; c++) {
        __half2 p0 = __float22half2_rn(v[c]);
        __half2 p1 = __float22half2_rn(v[c + 8]);
        __half2 p2 = __float22half2_rn(v[c + 16]);
        __half2 p3 = __float22half2_rn(v[c + 24]);
        uint4 pk = make_uint4(*(unsigned*)&p0, *(unsigned*)&p1,
                              *(unsigned*)&p2, *(unsigned*)&p3);
        *(uint4*)&g_circ[base + c * 512 + t * 4] = pk;
    }
}

// ---------------------------------------------------------------------------
// Kernel Bmid: all high-bit work of BOTH layers in one kernel.
// Tile = 8 low columns x 1024 rows j (stride 4096); 256 threads x 32 complex;
// 64 KB state smem (fp32) + 32 KB h tile = 96 KB dynamic, 2 CTAs/SM.
//   round 1 (fused coalesced load): layer-0 mixing, j bits 5..9
//   round 2:                        layer-0 mixing, j bits 0..4
//   phase(gamma1) from the prefetched smem h tile
//   round 3 (no exchange needed):   layer-1 mixing, j bits 0..4
//   round 4 (fused coalesced store):layer-1 mixing, j bits 5..9
// Global state accesses are exact 32B sectors (8 lanes x half2).
// ---------------------------------------------------------------------------
__global__ void __launch_bounds__(BTHREADS, 2)
kernelBmid(const float* __restrict__ h,
           const float* __restrict__ gamma,
           const float* __restrict__ beta)
{
    extern __shared__ float2 sst[];          // [0,8192) state  (64 KB)
    float* shh = (float*)(sst + 8192);       // 8192 floats h tile (32 KB)

    const int t       = threadIdx.x;
    const int l       = t & 7;
    const int jb      = t >> 3;              // 0..31
    const int lowbase = blockIdx.x << 3;
    const float cb0 = cosf(beta[0]), sb0 = sinf(beta[0]);
    const float cb1 = cosf(beta[1]), sb1 = sinf(beta[1]);
    const float g1  = gamma[1];
    float2 v[32];

    // Coalesced state load: j = k*32 + jb (8 lanes cover a 32B sector).
    #pragma unroll
    for (int k = 0; k < 32; k++)
        v[k] = ldState(((k * 32 + jb) << 12) + lowbase + l);
    // Prefetch h tile (overlaps with butterfly compute below).
    #pragma unroll
    for (int m = 0; m < 32; m++) {
        int i = t + m * 256;
        shh[phiH(i)] = h[((i >> 3) << 12) + lowbase + (i & 7)];
    }

    RADIX32(v, cb0, sb0);                              // layer0: j bits 5..9

    #pragma unroll
    for (int k = 0; k < 32; k++) sst[phiS(k * 256 + t)] = v[k];
    __syncthreads();
    #pragma unroll
    for (int k = 0; k < 32; k++) v[k] = sst[phiS(jb * 256 + k * 8 + l)];
    RADIX32(v, cb0, sb0);                              // layer0: j bits 0..4

    // Layer-1 cost phase; register k = j bits 0..4, so h index = jb*32+k.
    #pragma unroll
    for (int k = 0; k < 32; k++) {
        float hv = shh[phiH(jb * 256 + k * 8 + l)];
        float sp, cp;
        __sincosf(g1 * hv, &sp, &cp);
        v[k] = make_float2(v[k].x * cp - v[k].y * sp,
                           v[k].x * sp + v[k].y * cp);
    }

    RADIX32(v, cb1, sb1);                              // layer1: j bits 0..4
    __syncthreads();                                   // drain round-2 reads
    #pragma unroll
    for (int k = 0; k < 32; k++) sst[phiS(jb * 256 + k * 8 + l)] = v[k];
    __syncthreads();
    #pragma unroll
    for (int k = 0; k < 32; k++) v[k] = sst[phiS(k * 256 + t)];
    RADIX32(v, cb1, sb1);                              // layer1: j bits 5..9

    // Coalesced store, same pattern as the load.
    #pragma unroll
    for (int k = 0; k < 32; k++)
        stState(((k * 32 + jb) << 12) + lowbase + l, v[k]);
}

// ---------------------------------------------------------------------------
// Kernel A_reduce: layer-1 low-12 mixing + fused sum(|c|^2 * hS) * 2^-22.
// No state write-back; no separate finalize kernel — the last block to finish
// (completion counter) writes out[0] and resets the counter for the next
// graph replay.
// ---------------------------------------------------------------------------
__global__ void __launch_bounds__(ATHREADS, 4)
kernelA_reduce(const float* __restrict__ hS,
               const float* __restrict__ beta,
               float* __restrict__ out)
{
    __shared__ float2 sh[4096];     // 32 KB
    __shared__ float  hsh[4096];    // 16 KB
    __shared__ double wsum[ATHREADS / 32];

    const int t    = threadIdx.x;
    const int base = blockIdx.x << 12;
    const float cb = cosf(beta[1]);
    const float sb = sinf(beta[1]);
    float2 v[32];

    #pragma unroll
    for (int k = 0; k < 32; k++)                       // 128B/warp contiguous
        v[k] = ldState(base + k * 128 + t);
    #pragma unroll
    for (int m = 0; m < 32; m++)                       // prefetch hS tile
        hsh[t + m * 128] = hS[base + t + m * 128];

    RADIX32(v, cb, sb);                                // logical bits 7..11

    #pragma unroll
    for (int k = 0; k < 32; k++) sh[phi(t * 32 + k)] = v[k];
    __syncthreads();
    #pragma unroll
    for (int k = 0; k < 32; k++) v[k] = sh[phi(k * 128 + t)];
    RADIX32(v, cb, sb);                                // logical bits 2..6
    __syncthreads();

    #pragma unroll
    for (int k = 0; k < 32; k++) sh[phi(t * 32 + k)] = v[k];
    __syncthreads();
    #pragma unroll
    for (int k = 0; k < 32; k++) v[k] = sh[phi(k * 128 + t)];
    stage32(v, 8,  cb, sb);                            // logical bit 0
    stage32(v, 16, cb, sb);                            // logical bit 1

    // logical c*512 + t*4 + q -> v[c + 8*q]; hS from smem as float4.
    const float4* hs4 = (const float4*)hsh;
    float a0 = 0.0f, a1 = 0.0f;
    #pragma unroll
    for (int c = 0; c < 8; c++) {
        float4 s = hs4[c * 128 + t];
        a0 = fmaf(fmaf(v[c     ].x, v[c     ].x, v[c     ].y * v[c     ].y), s.x, a0);
        a1 = fmaf(fmaf(v[c +  8].x, v[c +  8].x, v[c +  8].y * v[c +  8].y), s.y, a1);
        a0 = fmaf(fmaf(v[c + 16].x, v[c + 16].x, v[c + 16].y * v[c + 16].y), s.z, a0);
        a1 = fmaf(fmaf(v[c + 24].x, v[c + 24].x, v[c + 24].y * v[c + 24].y), s.w, a1);
    }
    double acc = (double)a0 + (double)a1;
    #pragma unroll
    for (int o = 16; o > 0; o >>= 1)
        acc += __shfl_down_sync(0xffffffffu, acc, o);
    if ((t & 31) == 0) wsum[t >> 5] = acc;
    __syncthreads();
    if (t == 0) {
        atomicAdd(&g_sum, (wsum[0] + wsum[1]) + (wsum[2] + wsum[3]));
        __threadfence();
        unsigned done = atomicAdd(&g_count, 1u);
        if (done == gridDim.x - 1) {                   // last block finishes
            double total = atomicAdd(&g_sum, 0.0);     // acquire-read
            out[0] = (float)(total * (1.0 / 4194304.0));   // * 2^-22
            g_count = 0;                               // reset for next replay
        }
    }
}

extern "C" void kernel_launch(void* const* d_in, const int* in_sizes, int n_in,
                              void* d_out, int out_size)
{
    const float* h     = (const float*)d_in[0];
    const float* hS    = (const float*)d_in[1];
    const float* gamma = (const float*)d_in[2];
    const float* beta  = (const float*)d_in[3];
    float* out = (float*)d_out;

    const int smemB = 8192 * sizeof(float2) + 8192 * sizeof(float); // 96 KB
    cudaFuncSetAttribute((const void*)kernelBmid,
                         cudaFuncAttributeMaxDynamicSharedMemorySize, smemB);

    // Layer 0: init + phase(gamma0) + low-12 mixing (also zeroes g_sum)
    kernelA_init<<<1024, ATHREADS>>>(h, gamma, beta);
    // High-10 mixing of layer 0, phase(gamma1), high-10 mixing of layer 1
    kernelBmid<<<512, BTHREADS, smemB>>>(h, gamma, beta);
    // Layer 1: low-12 mixing + fused reduction + direct out[0] write
    kernelA_reduce<<<1024, ATHREADS>>>(hS, beta, out);
}

// round 15
// speedup vs baseline: 3.5371x; 1.0037x over previous
#include <cuda_runtime.h>
#include <cuda_fp16.h>
#include <math.h>

#define NSTATES (1 << 22)      // 4,194,304 amplitudes
#define ATHREADS 128           // kernelA: 32 complex per thread
#define BTHREADS 256           // kernelBmid: 32 complex per thread

// Inter-kernel statevector stored as half2 (16 MB), amplitudes UNNORMALIZED
// and WITHOUT the per-stage cos(beta) factors (tangent-factored butterflies);
// the exact scale 2^-22 * cb0^44 * cb1^44 is applied once at the end.
__device__ __half2 g_circ[NSTATES];
__device__ double  g_sum;
__device__ unsigned g_count;   // zero-init; reset by last block each run

__device__ __forceinline__ float2 ldState(int idx) {
    return __half22float2(g_circ[idx]);
}
__device__ __forceinline__ void stState(int idx, float2 v) {
    g_circ[idx] = __float22half2_rn(v);
}

// kernelA swizzle (radix-32, 128-thread patterns) — verified conflict-free.
__device__ __forceinline__ int phi(int a) {
    return a ^ ((a >> 5) & 15);
}
// kernelB state swizzle (float2 units): flip bit3 by j-bit5 (addr bit 8).
__device__ __forceinline__ int phiS(int a) {
    return a ^ (((a >> 8) & 1) << 3);
}
// kernelB h-tile swizzle (float units): spread jb across bank octets.
__device__ __forceinline__ int phiH(int a) {
    return a ^ (((a >> 8) & 3) << 3);
}

// Tangent-factored butterfly stage: Rx = cb*(I + i*tb*X), cb folded out.
// Per pair: a'' = a + i*tb*c ; c'' = c + i*tb*a  -> 4 FMA (was 4 MUL + 4 FMA).
__device__ __forceinline__ void stage32(float2* v, const int d, const float tb) {
    #pragma unroll
    for (int m = 0; m < 32; m++) if (!(m & d)) {
        float ax = v[m].x,     ay = v[m].y;
        float cx = v[m | d].x, cy = v[m | d].y;
        v[m].x     = fmaf(-tb, cy, ax);
        v[m].y     = fmaf( tb, cx, ay);
        v[m | d].x = fmaf(-tb, ay, cx);
        v[m | d].y = fmaf( tb, ax, cy);
    }
}
#define RADIX32(v, TB) { stage32(v,1,TB);  stage32(v,2,TB);  \
                         stage32(v,4,TB);  stage32(v,8,TB);  \
                         stage32(v,16,TB); }

// ---------------------------------------------------------------------------
// Kernel A_init: layer-0 phase + 12 stages over the low 12 bits; block = 4096
// contiguous amplitudes, 128 threads x 32 complex. Rounds 5+5+2 with the
// rotl5 storage relabeling. Synthesizes exp(i*gamma0*h) (unnormalized) in-
// register; also zeroes g_sum (stream-ordered).
// ---------------------------------------------------------------------------
__global__ void __launch_bounds__(ATHREADS, 4)
kernelA_init(const float* __restrict__ h,
             const float* __restrict__ gamma,
             const float* __restrict__ beta)
{
    __shared__ float2 sh[4096];   // 32 KB

    const int t    = threadIdx.x;
    const int base = blockIdx.x << 12;
    const float tb = tanf(beta[0]);
    float2 v[32];

    if (blockIdx.x == 0 && t == 0) g_sum = 0.0;
    {
        const float g0 = gamma[0];
        #pragma unroll
        for (int k = 0; k < 32; k++) {
            float sp, cp;
            __sincosf(g0 * h[base + k * 128 + t], &sp, &cp);
            v[k] = make_float2(cp, sp);                // unnormalized
        }
    }
    RADIX32(v, tb);                                    // logical bits 7..11

    #pragma unroll
    for (int k = 0; k < 32; k++) sh[phi(t * 32 + k)] = v[k];
    __syncthreads();
    #pragma unroll
    for (int k = 0; k < 32; k++) v[k] = sh[phi(k * 128 + t)];
    RADIX32(v, tb);                                    // logical bits 2..6
    __syncthreads();

    #pragma unroll
    for (int k = 0; k < 32; k++) sh[phi(t * 32 + k)] = v[k];
    __syncthreads();
    #pragma unroll
    for (int k = 0; k < 32; k++) v[k] = sh[phi(k * 128 + t)];
    stage32(v, 8,  tb);                                // logical bit 0
    stage32(v, 16, tb);                                // logical bit 1

    // logical = (k&7)*512 + t*4 + (k>>3): 4 half2 = 16B per (c), contiguous
    #pragma unroll
    for (int c = 0; c < 8; c++) {
        __half2 p0 = __float22half2_rn(v[c]);
        __half2 p1 = __float22half2_rn(v[c + 8]);
        __half2 p2 = __float22half2_rn(v[c + 16]);
        __half2 p3 = __float22half2_rn(v[c + 24]);
        uint4 pk = make_uint4(*(unsigned*)&p0, *(unsigned*)&p1,
                              *(unsigned*)&p2, *(unsigned*)&p3);
        *(uint4*)&g_circ[base + c * 512 + t * 4] = pk;
    }
}

// ---------------------------------------------------------------------------
// Kernel Bmid: all high-bit work of BOTH layers in one kernel.
// Tile = 8 low columns x 1024 rows j (stride 4096); 256 threads x 32 complex;
// 64 KB state smem (fp32) + 32 KB h tile = 96 KB dynamic, 2 CTAs/SM.
//   round 1 (fused coalesced load): layer-0 mixing, j bits 5..9
//   round 2:                        layer-0 mixing, j bits 0..4
//   phase(gamma1) from the prefetched smem h tile
//   round 3 (no exchange needed):   layer-1 mixing, j bits 0..4
//   round 4 (fused coalesced store):layer-1 mixing, j bits 5..9
// Global state accesses are exact 32B sectors (8 lanes x half2).
// ---------------------------------------------------------------------------
__global__ void __launch_bounds__(BTHREADS, 2)
kernelBmid(const float* __restrict__ h,
           const float* __restrict__ gamma,
           const float* __restrict__ beta)
{
    extern __shared__ float2 sst[];          // [0,8192) state  (64 KB)
    float* shh = (float*)(sst + 8192);       // 8192 floats h tile (32 KB)

    const int t       = threadIdx.x;
    const int l       = t & 7;
    const int jb      = t >> 3;              // 0..31
    const int lowbase = blockIdx.x << 3;
    const float tb0 = tanf(beta[0]);
    const float tb1 = tanf(beta[1]);
    const float g1  = gamma[1];
    float2 v[32];

    // Coalesced state load: j = k*32 + jb (8 lanes cover a 32B sector).
    #pragma unroll
    for (int k = 0; k < 32; k++)
        v[k] = ldState(((k * 32 + jb) << 12) + lowbase + l);
    // Prefetch h tile (overlaps with butterfly compute below).
    #pragma unroll
    for (int m = 0; m < 32; m++) {
        int i = t + m * 256;
        shh[phiH(i)] = h[((i >> 3) << 12) + lowbase + (i & 7)];
    }

    RADIX32(v, tb0);                                   // layer0: j bits 5..9

    #pragma unroll
    for (int k = 0; k < 32; k++) sst[phiS(k * 256 + t)] = v[k];
    __syncthreads();
    #pragma unroll
    for (int k = 0; k < 32; k++) v[k] = sst[phiS(jb * 256 + k * 8 + l)];
    RADIX32(v, tb0);                                   // layer0: j bits 0..4

    // Layer-1 cost phase; register k = j bits 0..4, so h index = jb*32+k.
    #pragma unroll
    for (int k = 0; k < 32; k++) {
        float hv = shh[phiH(jb * 256 + k * 8 + l)];
        float sp, cp;
        __sincosf(g1 * hv, &sp, &cp);
        v[k] = make_float2(v[k].x * cp - v[k].y * sp,
                           v[k].x * sp + v[k].y * cp);
    }

    RADIX32(v, tb1);                                   // layer1: j bits 0..4
    __syncthreads();                                   // drain round-2 reads
    #pragma unroll
    for (int k = 0; k < 32; k++) sst[phiS(jb * 256 + k * 8 + l)] = v[k];
    __syncthreads();
    #pragma unroll
    for (int k = 0; k < 32; k++) v[k] = sst[phiS(k * 256 + t)];
    RADIX32(v, tb1);                                   // layer1: j bits 5..9

    // Coalesced store, same pattern as the load.
    #pragma unroll
    for (int k = 0; k < 32; k++)
        stState(((k * 32 + jb) << 12) + lowbase + l, v[k]);
}

// ---------------------------------------------------------------------------
// Kernel A_reduce: layer-1 low-12 mixing + fused sum(|c|^2 * hS), scaled by
// 2^-22 * cb0^44 * cb1^44 (tangent-factorization correction). Last block
// (completion counter) writes out[0] and resets the counter.
// ---------------------------------------------------------------------------
__global__ void __launch_bounds__(ATHREADS, 4)
kernelA_reduce(const float* __restrict__ hS,
               const float* __restrict__ beta,
               float* __restrict__ out)
{
    __shared__ float2 sh[4096];     // 32 KB
    __shared__ float  hsh[4096];    // 16 KB
    __shared__ double wsum[ATHREADS / 32];

    const int t    = threadIdx.x;
    const int base = blockIdx.x << 12;
    const float tb = tanf(beta[1]);
    float2 v[32];

    #pragma unroll
    for (int k = 0; k < 32; k++)                       // 128B/warp contiguous
        v[k] = ldState(base + k * 128 + t);
    #pragma unroll
    for (int m = 0; m < 32; m++)                       // prefetch hS tile
        hsh[t + m * 128] = hS[base + t + m * 128];

    RADIX32(v, tb);                                    // logical bits 7..11

    #pragma unroll
    for (int k = 0; k < 32; k++) sh[phi(t * 32 + k)] = v[k];
    __syncthreads();
    #pragma unroll
    for (int k = 0; k < 32; k++) v[k] = sh[phi(k * 128 + t)];
    RADIX32(v, tb);                                    // logical bits 2..6
    __syncthreads();

    #pragma unroll
    for (int k = 0; k < 32; k++) sh[phi(t * 32 + k)] = v[k];
    __syncthreads();
    #pragma unroll
    for (int k = 0; k < 32; k++) v[k] = sh[phi(k * 128 + t)];
    stage32(v, 8,  tb);                                // logical bit 0
    stage32(v, 16, tb);                                // logical bit 1

    // logical c*512 + t*4 + q -> v[c + 8*q]; hS from smem as float4.
    const float4* hs4 = (const float4*)hsh;
    float a0 = 0.0f, a1 = 0.0f;
    #pragma unroll
    for (int c = 0; c < 8; c++) {
        float4 s = hs4[c * 128 + t];
        a0 = fmaf(fmaf(v[c     ].x, v[c     ].x, v[c     ].y * v[c     ].y), s.x, a0);
        a1 = fmaf(fmaf(v[c +  8].x, v[c +  8].x, v[c +  8].y * v[c +  8].y), s.y, a1);
        a0 = fmaf(fmaf(v[c + 16].x, v[c + 16].x, v[c + 16].y * v[c + 16].y), s.z, a0);
        a1 = fmaf(fmaf(v[c + 24].x, v[c + 24].x, v[c + 24].y * v[c + 24].y), s.w, a1);
    }
    double acc = (double)a0 + (double)a1;
    #pragma unroll
    for (int o = 16; o > 0; o >>= 1)
        acc += __shfl_down_sync(0xffffffffu, acc, o);
    if ((t & 31) == 0) wsum[t >> 5] = acc;
    __syncthreads();
    if (t == 0) {
        atomicAdd(&g_sum, (wsum[0] + wsum[1]) + (wsum[2] + wsum[3]));
        __threadfence();
        unsigned done = atomicAdd(&g_count, 1u);
        if (done == gridDim.x - 1) {                   // last block finishes
            double total = atomicAdd(&g_sum, 0.0);     // acquire-read
            double c0 = cos((double)beta[0]);
            double c1 = cos((double)beta[1]);
            double scale = (1.0 / 4194304.0) * pow(c0, 44.0) * pow(c1, 44.0);
            out[0] = (float)(total * scale);
            g_count = 0;                               // reset for next replay
        }
    }
}

extern "C" void kernel_launch(void* const* d_in, const int* in_sizes, int n_in,
                              void* d_out, int out_size)
{
    const float* h     = (const float*)d_in[0];
    const float* hS    = (const float*)d_in[1];
    const float* gamma = (const float*)d_in[2];
    const float* beta  = (const float*)d_in[3];
    float* out = (float*)d_out;

    const int smemB = 8192 * sizeof(float2) + 8192 * sizeof(float); // 96 KB
    cudaFuncSetAttribute((const void*)kernelBmid,
                         cudaFuncAttributeMaxDynamicSharedMemorySize, smemB);

    // Layer 0: init + phase(gamma0) + low-12 mixing (also zeroes g_sum)
    kernelA_init<<<1024, ATHREADS>>>(h, gamma, beta);
    // High-10 mixing of layer 0, phase(gamma1), high-10 mixing of layer 1
    kernelBmid<<<512, BTHREADS, smemB>>>(h, gamma, beta);
    // Layer 1: low-12 mixing + fused reduction + direct out[0] write
    kernelA_reduce<<<1024, ATHREADS>>>(hS, beta, out);
}